// round 2
// baseline (speedup 1.0000x reference)
#include <cuda_runtime.h>
#include <cuda_bf16.h>

#define N_NODES 100000
#define N_EDGES 1600000
#define IN_DIM  256
#define HIDDEN  64

// Scratch (allocation-free rule: __device__ globals)
__device__ __align__(16) float g_u[IN_DIM];   // W @ w2
__device__ float g_c;                          // b.w2 + b2
__device__ float g_deg[N_NODES];               // degree incl. self loop
__device__ float g_ss[N_NODES];                // s[v] * dinv[v]
__device__ float g_dinv[N_NODES];
__device__ float g_t[N_NODES];                 // edge-aggregated ss[src]
__device__ int   g_is64;                       // edge_index element width flag

// K0: sniff edge_index dtype. int64 little-endian with values < 2^31:
// every odd 32-bit word is zero. int32: odd words are real indices.
__global__ void k_sniff(const unsigned* __restrict__ ew) {
    if (threadIdx.x == 0) {
        int all_zero = 1;
        for (int i = 1; i < 128; i += 2) all_zero &= (ew[i] == 0u);
        g_is64 = all_zero;
    }
}

__device__ __forceinline__ int load_idx(const void* base, long long e, int is64) {
    return is64 ? (int)((const long long*)base)[e] : ((const int*)base)[e];
}

// K1: u = W @ w2  (256 threads), c = b.w2 + b2
__global__ void k_proj(const float* __restrict__ W, const float* __restrict__ b,
                       const float* __restrict__ w2, const float* __restrict__ b2) {
    int i = threadIdx.x;
    float acc = 0.f;
#pragma unroll
    for (int h = 0; h < HIDDEN; h++) acc += W[i * HIDDEN + h] * w2[h];
    g_u[i] = acc;
    if (i == 0) {
        float cc = b2[0];
        for (int h = 0; h < HIDDEN; h++) cc += b[h] * w2[h];
        g_c = cc;
    }
}

// K2: init deg=1 (self loop), t=0
__global__ void k_init() {
    int v = blockIdx.x * blockDim.x + threadIdx.x;
    if (v < N_NODES) { g_deg[v] = 1.0f; g_t[v] = 0.0f; }
}

// K3: degree count over dst row (dst = second row of edge_index)
__global__ void k_deg(const void* __restrict__ ei) {
    int e = blockIdx.x * blockDim.x + threadIdx.x;
    if (e < N_EDGES) {
        int is64 = g_is64;
        int d = load_idx(ei, (long long)N_EDGES + e, is64);
        if ((unsigned)d < (unsigned)N_NODES) atomicAdd(&g_deg[d], 1.0f);
    }
}

// K4: warp per node: s[v] = x[v].u ; ss = s*dinv ; dinv stored
__global__ void k_dot(const float* __restrict__ x) {
    int gtid = blockIdx.x * blockDim.x + threadIdx.x;
    int warp = gtid >> 5;
    int lane = threadIdx.x & 31;
    if (warp >= N_NODES) return;
    const float4* xp = (const float4*)(x + (size_t)warp * IN_DIM);
    const float4* up = (const float4*)g_u;
    float4 a0 = xp[lane];
    float4 u0 = up[lane];
    float4 a1 = xp[lane + 32];
    float4 u1 = up[lane + 32];
    float acc = a0.x * u0.x + a0.y * u0.y + a0.z * u0.z + a0.w * u0.w
              + a1.x * u1.x + a1.y * u1.y + a1.z * u1.z + a1.w * u1.w;
#pragma unroll
    for (int o = 16; o; o >>= 1) acc += __shfl_xor_sync(0xffffffffu, acc, o);
    if (lane == 0) {
        float di = rsqrtf(g_deg[warp]);
        g_dinv[warp] = di;
        g_ss[warp] = acc * di;
    }
}

// K5: scatter ss[src] into t[dst]
__global__ void k_scatter(const void* __restrict__ ei) {
    int e = blockIdx.x * blockDim.x + threadIdx.x;
    if (e < N_EDGES) {
        int is64 = g_is64;
        int s = load_idx(ei, e, is64);
        int d = load_idx(ei, (long long)N_EDGES + e, is64);
        if ((unsigned)s < (unsigned)N_NODES && (unsigned)d < (unsigned)N_NODES)
            atomicAdd(&g_t[d], g_ss[s]);
    }
}

// K6: out = sigmoid(dinv*(t + ss) + c)
__global__ void k_out(float* __restrict__ out) {
    int v = blockIdx.x * blockDim.x + threadIdx.x;
    if (v < N_NODES) {
        float z = g_dinv[v] * (g_t[v] + g_ss[v]) + g_c;
        out[v] = 1.0f / (1.0f + expf(-z));
    }
}

extern "C" void kernel_launch(void* const* d_in, const int* in_sizes, int n_in,
                              void* d_out, int out_size) {
    const float* x   = (const float*)d_in[0];
    const void*  ei  = d_in[1];                 // [2, N_EDGES], int64 or int32 (sniffed)
    const float* W   = (const float*)d_in[2];
    const float* b   = (const float*)d_in[3];
    const float* w2  = (const float*)d_in[4];
    const float* b2  = (const float*)d_in[5];
    float*       out = (float*)d_out;

    k_sniff<<<1, 32>>>((const unsigned*)ei);
    k_proj<<<1, IN_DIM>>>(W, b, w2, b2);
    k_init<<<(N_NODES + 255) / 256, 256>>>();
    k_deg<<<(N_EDGES + 255) / 256, 256>>>(ei);
    k_dot<<<(N_NODES * 32 + 255) / 256, 256>>>(x);
    k_scatter<<<(N_EDGES + 255) / 256, 256>>>(ei);
    k_out<<<(N_NODES + 255) / 256, 256>>>(out);
}